// round 7
// baseline (speedup 1.0000x reference)
#include <cuda_runtime.h>
#include <cstdint>

#define DHN 512
#define BN  64
#define TN  1024
#define CLUSTER 8
#define HPC 64
#define RPAD 68
#define RSTRD (8*RPAD)            // 544 floats per (group,buf,bb) row
#define WREG 40                   // W floats per thread in registers
#define WSM  24                   // W floats per thread in smem
#define WROW 28                   // padded smem row (24 data + 4 pad)
#define SMEM_W_FLOATS (512*WROW)              // 14336 floats
#define SMEM_R_FLOATS (8*RSTRD)               // 4352 floats: [g][buf][bb][RSTRD]
#define SMEM_BYTES ((SMEM_W_FLOATS + SMEM_R_FLOATS)*4 + 64)

__device__ float g_sig[(size_t)BN*DHN*TN];    // sigma(x_new) for rnn_out
__device__ float g_part[4][BN][TN];

__device__ __forceinline__ float sigmoidf_(float x){ return 1.0f/(1.0f + __expf(-x)); }

__device__ __forceinline__ unsigned long long pack2(float lo, float hi){
    unsigned long long r; asm("mov.b64 %0, {%1,%2};" : "=l"(r) : "f"(lo), "f"(hi)); return r;
}
__device__ __forceinline__ void unpack2(unsigned long long v, float &lo, float &hi){
    asm("mov.b64 {%0,%1}, %2;" : "=f"(lo), "=f"(hi) : "l"(v));
}
__device__ __forceinline__ void fma2(unsigned long long &acc, unsigned long long a, unsigned long long b){
    asm("fma.rn.f32x2 %0, %1, %2, %3;" : "=l"(acc) : "l"(a), "l"(b), "l"(acc));
}
__device__ __forceinline__ uint32_t smem_u32(const void* p){
    uint32_t a; asm("{ .reg .u64 t; cvta.to.shared.u64 t, %1; cvt.u32.u64 %0, t; }" : "=r"(a) : "l"(p)); return a;
}
__device__ __forceinline__ uint32_t mapa_(uint32_t addr, uint32_t rank){
    uint32_t r; asm("mapa.shared::cluster.u32 %0, %1, %2;" : "=r"(r) : "r"(addr), "r"(rank)); return r;
}
__device__ __forceinline__ void st_cluster_f32(uint32_t addr, float v){
    asm volatile("st.shared::cluster.f32 [%0], %1;" :: "r"(addr), "f"(v) : "memory");
}
__device__ __forceinline__ void cluster_sync_(){
    asm volatile("barrier.cluster.arrive.aligned;" ::: "memory");
    asm volatile("barrier.cluster.wait.aligned;" ::: "memory");
}
__device__ __forceinline__ uint32_t ctarank_(){
    uint32_t r; asm("mov.u32 %0, %%cluster_ctarank;" : "=r"(r)); return r;
}
__device__ __forceinline__ void mbar_init(uint32_t a, uint32_t cnt){
    asm volatile("mbarrier.init.shared.b64 [%0], %1;" :: "r"(a), "r"(cnt) : "memory");
}
// release at cluster scope: makes this CTA's prior (bar.sync-collected) remote
// stores visible to the waiting CTA's acquire.
__device__ __forceinline__ void mbar_arrive_remote(uint32_t remote_addr){
    asm volatile("mbarrier.arrive.release.cluster.shared::cluster.b64 _, [%0];"
                 :: "r"(remote_addr) : "memory");
}
__device__ __forceinline__ void mbar_wait(uint32_t a, uint32_t parity){
    uint32_t done;
    asm volatile("{\n\t.reg .pred p;\n\t"
        "mbarrier.try_wait.parity.acquire.cluster.shared::cta.b64 p, [%1], %2;\n\t"
        "selp.b32 %0,1,0,p;\n\t}" : "=r"(done) : "r"(a), "r"(parity) : "memory");
    while (!done){
        asm volatile("{\n\t.reg .pred p;\n\t"
            "mbarrier.try_wait.parity.acquire.cluster.shared::cta.b64 p, [%1], %2, 0x989680;\n\t"
            "selp.b32 %0,1,0,p;\n\t}" : "=r"(done) : "r"(a), "r"(parity) : "memory");
    }
}

// 16 clusters x 8 CTAs x 512 threads. CTA owns 64 h-rows; cluster owns 4 batches
// split into pipeline groups A={b0,b1}, B={b2,b3}.
// Thread tid = h_local*8 + dg owns W[hg, dg*64 .. dg*64+64):
//   d 0..39 in 20 f32x2 regs, d 40..63 in a pad-28 smem row.
__global__ void __cluster_dims__(CLUSTER,1,1) __launch_bounds__(512,1)
rnn_main(const float* __restrict__ u, const float* __restrict__ r0,
         const float* __restrict__ noise, const float* __restrict__ win,
         const float* __restrict__ w_raw, const float* __restrict__ taus,
         float* __restrict__ xs)
{
    extern __shared__ __align__(16) float smem[];
    float* W_sh  = smem;
    float* rbufs = smem + SMEM_W_FLOATS;
    const uint32_t mb_base = smem_u32(rbufs + SMEM_R_FLOATS);  // 4 mbars: (g*2+buf)*8

    const int tid = threadIdx.x;
    const int h_local = tid >> 3;
    const int dg = tid & 7;
    const uint32_t rank = ctarank_();
    const int cid = blockIdx.x / CLUSTER;
    const int hg = (int)rank * HPC + h_local;
    const int bbase = cid * 4;

    // ---- W = |_w| (m is diag(+-1)) ----
    unsigned long long w2p[20];
    {
        const float* wr = w_raw + (size_t)hg * DHN + dg*64;
        #pragma unroll
        for (int k = 0; k < 20; k++)
            w2p[k] = pack2(fabsf(wr[2*k]), fabsf(wr[2*k+1]));
        float* wsm = W_sh + tid*WROW;
        #pragma unroll
        for (int j = 0; j < WSM; j++)
            wsm[j] = fabsf(wr[WREG + j]);
    }
    const float a_h   = 1.0f / taus[hg];
    const float win_h = win[hg];

    if (tid == 0){
        #pragma unroll
        for (int q = 0; q < 4; q++) mbar_init(mb_base + q*8, CLUSTER);
    }
    __syncthreads();

    // Epilogue lane (dg<2): group A batch bbase+dg, group B batch bbase+2+dg
    const int bb = dg & 1;
    const int bgA = bbase + bb;
    const int bgB = bbase + 2 + bb;
    float sA = 0.0f, sB = 0.0f;

    uint32_t slotA[2], slotB[2];
    {
        const int off = (int)rank*RPAD + h_local;
        slotA[0] = smem_u32(rbufs + ((0*2+0)*2 + bb)*RSTRD + off);
        slotA[1] = smem_u32(rbufs + ((0*2+1)*2 + bb)*RSTRD + off);
        slotB[0] = smem_u32(rbufs + ((1*2+0)*2 + bb)*RSTRD + off);
        slotB[1] = smem_u32(rbufs + ((1*2+1)*2 + bb)*RSTRD + off);
    }

    // ---- Prologue: broadcast sigmoid(r0) into buf 0 of both groups ----
    if (dg < 2){
        sA = r0[(size_t)bgA*DHN + hg];
        sB = r0[(size_t)bgB*DHN + hg];
        float rvA = sigmoidf_(sA), rvB = sigmoidf_(sB);
        #pragma unroll
        for (int p = 0; p < 8; p++){
            st_cluster_f32(mapa_(slotA[0], (uint32_t)p), rvA);
            st_cluster_f32(mapa_(slotB[0], (uint32_t)p), rvB);
        }
    }
    cluster_sync_();   // initial buffers + mbar inits visible cluster-wide

    float* xsA  = xs    + ((size_t)bgA*DHN + hg)*TN;
    float* sigA = g_sig + ((size_t)bgA*DHN + hg)*TN;
    float* xsB  = xs    + ((size_t)bgB*DHN + hg)*TN;
    float* sigB = g_sig + ((size_t)bgB*DHN + hg)*TN;

#define MATVEC(gidx, jbuf, SUM0, SUM1) do {                                   \
    const float* rb0 = rbufs + (((gidx)*2+(jbuf))*2 + 0)*RSTRD + dg*RPAD;     \
    const float* rb1 = rbufs + (((gidx)*2+(jbuf))*2 + 1)*RSTRD + dg*RPAD;     \
    unsigned long long a00=0ull,a01=0ull,a10=0ull,a11=0ull;                   \
    const ulonglong2* rp0 = (const ulonglong2*)rb0;                           \
    const ulonglong2* rp1 = (const ulonglong2*)rb1;                           \
    _Pragma("unroll")                                                         \
    for (int k = 0; k < 10; k++){                                             \
        ulonglong2 v0 = rp0[k]; ulonglong2 v1 = rp1[k];                       \
        fma2(a00, w2p[2*k],   v0.x); fma2(a01, w2p[2*k+1], v0.y);             \
        fma2(a10, w2p[2*k],   v1.x); fma2(a11, w2p[2*k+1], v1.y);             \
    }                                                                         \
    const ulonglong2* wp2 = (const ulonglong2*)(W_sh + tid*WROW);             \
    const ulonglong2* rq0 = (const ulonglong2*)(rb0 + WREG);                  \
    const ulonglong2* rq1 = (const ulonglong2*)(rb1 + WREG);                  \
    _Pragma("unroll")                                                         \
    for (int k = 0; k < 6; k++){                                              \
        ulonglong2 wv = wp2[k];                                               \
        ulonglong2 v0 = rq0[k]; ulonglong2 v1 = rq1[k];                       \
        fma2(a00, wv.x, v0.x); fma2(a01, wv.y, v0.y);                         \
        fma2(a10, wv.x, v1.x); fma2(a11, wv.y, v1.y);                         \
    }                                                                         \
    { float l0,h0,l1,h1;                                                      \
      unpack2(a00,l0,h0); unpack2(a01,l1,h1); SUM0 = (l0+h0)+(l1+h1);         \
      unpack2(a10,l0,h0); unpack2(a11,l1,h1); SUM1 = (l0+h0)+(l1+h1); }       \
    SUM0 += __shfl_xor_sync(0xffffffffu, SUM0, 1);                            \
    SUM0 += __shfl_xor_sync(0xffffffffu, SUM0, 2);                            \
    SUM0 += __shfl_xor_sync(0xffffffffu, SUM0, 4);                            \
    SUM1 += __shfl_xor_sync(0xffffffffu, SUM1, 1);                            \
    SUM1 += __shfl_xor_sync(0xffffffffu, SUM1, 2);                            \
    SUM1 += __shfl_xor_sync(0xffffffffu, SUM1, 4);                            \
} while (0)

    for (int t = 0; t < TN; t++){
        const int j = t & 1, nj = j ^ 1;
        const uint32_t par = (uint32_t)(((t - 1) >> 1) & 1);

        // Prefetch both phases' per-step inputs before any wait
        float nAv=0.f, uAv=0.f, nBv=0.f, uBv=0.f;
        if (dg < 2){
            nAv = noise[((size_t)t*BN + bgA)*DHN + hg];
            uAv = u[(size_t)bgA*TN + t];
            nBv = noise[((size_t)t*BN + bgB)*DHN + hg];
            uBv = u[(size_t)bgB*TN + t];
        }

        // ---------- phase A ----------
        if (t) mbar_wait(mb_base + (0*2 + j)*8, par);
        {
            float s0, s1;
            MATVEC(0, j, s0, s1);
            if (dg < 2){
                float dot = bb ? s1 : s0;
                float xn  = (1.0f - a_h)*sA + a_h*dot + win_h*uAv + 0.1f*nAv;
                xsA[t] = xn;
                sA = sigmoidf_(xn);
                sigA[t] = sA;
                float rv = sigmoidf_(sA);
                const uint32_t lb = slotA[nj];
                #pragma unroll
                for (int p = 0; p < 8; p++) st_cluster_f32(mapa_(lb, (uint32_t)p), rv);
            }
        }
        __syncthreads();
        if (tid < 8) mbar_arrive_remote(mapa_(mb_base + (0*2 + nj)*8, (uint32_t)tid));

        // ---------- phase B ----------
        if (t) mbar_wait(mb_base + (1*2 + j)*8, par);
        {
            float s0, s1;
            MATVEC(1, j, s0, s1);
            if (dg < 2){
                float dot = bb ? s1 : s0;
                float xn  = (1.0f - a_h)*sB + a_h*dot + win_h*uBv + 0.1f*nBv;
                xsB[t] = xn;
                sB = sigmoidf_(xn);
                sigB[t] = sB;
                float rv = sigmoidf_(sB);
                const uint32_t lb = slotB[nj];
                #pragma unroll
                for (int p = 0; p < 8; p++) st_cluster_f32(mapa_(lb, (uint32_t)p), rv);
            }
        }
        __syncthreads();
        if (tid < 8) mbar_arrive_remote(mapa_(mb_base + (1*2 + nj)*8, (uint32_t)tid));
    }

    cluster_sync_();   // no CTA exits while peers' remote stores/arrives in flight
#undef MATVEC
}

// Partial dot products over 128-h chunks: pure DRAM streaming, zero MUFU.
__global__ void __launch_bounds__(256)
rnn_out_part(const float* __restrict__ wout)
{
    const int b  = blockIdx.x >> 2;
    const int hc = blockIdx.x & 3;
    __shared__ float wsh[128];
    if (threadIdx.x < 128) wsh[threadIdx.x] = wout[hc*128 + threadIdx.x];
    __syncthreads();

    const float4* base = (const float4*)(g_sig + ((size_t)b*DHN + hc*128)*TN);
    float a0=0.f, a1=0.f, a2=0.f, a3=0.f;
    #pragma unroll 4
    for (int h = 0; h < 128; h++){
        float wv = wsh[h];
        float4 v = base[(size_t)h*(TN/4) + threadIdx.x];
        a0 = fmaf(wv, v.x, a0);
        a1 = fmaf(wv, v.y, a1);
        a2 = fmaf(wv, v.z, a2);
        a3 = fmaf(wv, v.w, a3);
    }
    float4 o; o.x=a0; o.y=a1; o.z=a2; o.w=a3;
    ((float4*)g_part[hc][b])[threadIdx.x] = o;
}

__global__ void __launch_bounds__(256)
rnn_combine(const float* __restrict__ bias, float* __restrict__ out)
{
    const int b = blockIdx.x;
    float4 p0 = ((const float4*)g_part[0][b])[threadIdx.x];
    float4 p1 = ((const float4*)g_part[1][b])[threadIdx.x];
    float4 p2 = ((const float4*)g_part[2][b])[threadIdx.x];
    float4 p3 = ((const float4*)g_part[3][b])[threadIdx.x];
    float bz = bias[0];
    float4 o;
    o.x = (p0.x+p1.x)+(p2.x+p3.x)+bz;
    o.y = (p0.y+p1.y)+(p2.y+p3.y)+bz;
    o.z = (p0.z+p1.z)+(p2.z+p3.z)+bz;
    o.w = (p0.w+p1.w)+(p2.w+p3.w)+bz;
    ((float4*)(out + (size_t)b*TN))[threadIdx.x] = o;
}

extern "C" void kernel_launch(void* const* d_in, const int* in_sizes, int n_in,
                              void* d_out, int out_size)
{
    // metadata order: u, r0, noise, win, m, wout, _w, taus, bias
    const float* u     = (const float*)d_in[0];
    const float* r0    = (const float*)d_in[1];
    const float* noise = (const float*)d_in[2];
    const float* win   = (const float*)d_in[3];
    const float* wout  = (const float*)d_in[5];
    const float* w_raw = (const float*)d_in[6];
    const float* taus  = (const float*)d_in[7];
    const float* bias  = (const float*)d_in[8];

    float* out = (float*)d_out;                 // outputs (B, T, 1)
    float* xs  = out + (size_t)BN * TN;         // xs (B, DH, T)

    static int smem_set = 0;
    if (!smem_set){
        cudaFuncSetAttribute(rnn_main, cudaFuncAttributeMaxDynamicSharedMemorySize, SMEM_BYTES);
        smem_set = 1;
    }

    rnn_main<<<16*CLUSTER, 512, SMEM_BYTES>>>(u, r0, noise, win, w_raw, taus, xs);
    rnn_out_part<<<BN*4, 256>>>(wout);
    rnn_combine<<<BN, 256>>>(bias, out);
}